// round 5
// baseline (speedup 1.0000x reference)
#include <cuda_runtime.h>

using ull = unsigned long long;

// ---------- packed f32x2 + MUFU helpers ----------
__device__ __forceinline__ ull pk2(float lo, float hi) {
    ull r; asm("mov.b64 %0, {%1, %2};" : "=l"(r) : "f"(lo), "f"(hi)); return r;
}
__device__ __forceinline__ void upk2(ull v, float& lo, float& hi) {
    asm("mov.b64 {%0, %1}, %2;" : "=f"(lo), "=f"(hi) : "l"(v));
}
__device__ __forceinline__ ull fma2(ull a, ull b, ull c) {
    ull d; asm("fma.rn.f32x2 %0, %1, %2, %3;" : "=l"(d) : "l"(a), "l"(b), "l"(c)); return d;
}
__device__ __forceinline__ ull add2(ull a, ull b) {
    ull d; asm("add.rn.f32x2 %0, %1, %2;" : "=l"(d) : "l"(a), "l"(b)); return d;
}
__device__ __forceinline__ ull mul2(ull a, ull b) {
    ull d; asm("mul.rn.f32x2 %0, %1, %2;" : "=l"(d) : "l"(a), "l"(b)); return d;
}
__device__ __forceinline__ float tanhf_hw(float x) {
    float y; asm("tanh.approx.f32 %0, %1;" : "=f"(y) : "f"(x)); return y;
}

#define HID 10
#define PF  4

// Layout: 10 lanes per *pair* of batch elements. Lane j of a group owns
// hidden unit j for elements (b, b+1); all packed f32x2 math is over the
// element pair -> 2 independent recurrence chains per thread (ILP-2).
// Each lane computes 4 gate rows (i,f,g,o) as packed dots with
// register-resident weights duplicated into both lanes. Sigmoids via
// 0.5*(1+tanh(x/2)) with the 0.5 folded into i/f/o weights -> 1 MUFU/gate.
// 3 pairs per warp (6 elems), lanes 30,31 duplicate/masked.
__global__ void __launch_bounds__(32, 8)
lstm_pair_kernel(const float* __restrict__ x,
                 const float* __restrict__ w_ih,
                 const float* __restrict__ w_hh,
                 const float* __restrict__ b_ih,
                 const float* __restrict__ b_hh,
                 const float* __restrict__ fc_w,
                 const float* __restrict__ fc_b,
                 float* __restrict__ out,
                 int S, int B)
{
    const int lane = threadIdx.x & 31;
    const int wg   = blockIdx.x;

    int grp = lane / HID; if (grp > 2) grp = 2;            // lanes 30,31 -> grp 2
    int j   = lane - grp * HID; if (j >= HID) j = HID - 1; // clamp dup lanes
    const int gbase = grp * HID;

    int b0 = wg * 6 + grp * 2;                 // even pair base
    const bool live = (b0 < B) && (lane < 30);
    if (b0 > B - 2) b0 = B - 2;                // safe-load clamp (B even)

    // ---- per-lane packed weights: value duplicated into both f32x2 lanes.
    // rows: 0=i(x0.5), 1=f(x0.5), 2=g(x1), 3=o(x0.5)
    ull whh[4][HID], wxd[4], bd[4];
#pragma unroll
    for (int r = 0; r < 4; ++r) {
        const float sc = (r == 2) ? 1.0f : 0.5f;
        const int row = r * HID + j;
#pragma unroll
        for (int k = 0; k < HID; ++k) {
            const float w = sc * w_hh[row * HID + k];
            whh[r][k] = pk2(w, w);
        }
        const float wx = sc * w_ih[row];
        const float bb = sc * (b_ih[row] + b_hh[row]);
        wxd[r] = pk2(wx, wx);
        bd[r]  = pk2(bb, bb);
    }

    ull fcd[HID];
#pragma unroll
    for (int k = 0; k < HID; ++k) { const float f = fc_w[k]; fcd[k] = pk2(f, f); }
    const float fb = fc_b[0];
    const ull half2 = pk2(0.5f, 0.5f);

    // ---- state: packed over the element pair ----
    ull hd[HID];
#pragma unroll
    for (int k = 0; k < HID; ++k) hd[k] = 0ull;
    ull c2 = 0ull;

    // ---- x prefetch pipeline: float2 (xP, xQ), PF deep ----
    float2 xbuf[PF];
#pragma unroll
    for (int i = 0; i < PF; ++i) {
        int ti = (i < S) ? i : (S - 1);
        xbuf[i] = __ldg((const float2*)(x + (size_t)ti * B + b0));
    }

    float* op = out + b0;

    for (int t = 0; t < S; t += PF) {
#pragma unroll
        for (int u = 0; u < PF; ++u) {
            const float2 xt = xbuf[u];
            int tn = t + u + PF; tn = (tn < S) ? tn : (S - 1);
            xbuf[u] = __ldg((const float2*)(x + (size_t)tn * B + b0));

            const ull xd = pk2(xt.x, xt.y);

            // 4 gate rows, each a packed-over-elements dot with 2-way k-split
            ull acc[4];
#pragma unroll
            for (int r = 0; r < 4; ++r) {
                ull a0 = fma2(xd, wxd[r], bd[r]);
                ull a1 = fma2(hd[1], whh[r][1], 0ull);
#pragma unroll
                for (int k = 0; k < HID; k += 2) a0 = fma2(hd[k], whh[r][k], a0);
#pragma unroll
                for (int k = 3; k < HID; k += 2) a1 = fma2(hd[k], whh[r][k], a1);
                acc[r] = add2(a0, a1);
            }

            // activations: scalar MUFU.TANH, repacked for packed cell update
            float pA, pB;
            upk2(acc[0], pA, pB);
            const ull ia2 = fma2(pk2(tanhf_hw(pA), tanhf_hw(pB)), half2, half2);
            upk2(acc[1], pA, pB);
            const ull fa2 = fma2(pk2(tanhf_hw(pA), tanhf_hw(pB)), half2, half2);
            upk2(acc[2], pA, pB);
            const ull ga2 = pk2(tanhf_hw(pA), tanhf_hw(pB));
            upk2(acc[3], pA, pB);
            const ull oa2 = fma2(pk2(tanhf_hw(pA), tanhf_hw(pB)), half2, half2);

            c2 = fma2(ia2, ga2, mul2(fa2, c2));

            float cP, cQ;
            upk2(c2, cP, cQ);
            const ull hn2 = mul2(oa2, pk2(tanhf_hw(cP), tanhf_hw(cQ)));

            float hnP, hnQ;
            upk2(hn2, hnP, hnQ);

            // broadcast the group's 10 (hP,hQ) pairs; fuse repack + fc head
            ull y2 = pk2(fb, fb);
#pragma unroll
            for (int m = 0; m < HID; ++m) {
                const float hP = __shfl_sync(0xffffffffu, hnP, gbase + m, 32);
                const float hQ = __shfl_sync(0xffffffffu, hnQ, gbase + m, 32);
                const ull hp = pk2(hP, hQ);
                hd[m] = hp;
                y2 = fma2(hp, fcd[m], y2);
            }

            if (live && j == 0) {
                float yP, yQ;
                upk2(y2, yP, yQ);
                *(float2*)op = make_float2(yP, yQ);
            }
            op += B;
        }
    }
}

extern "C" void kernel_launch(void* const* d_in, const int* in_sizes, int n_in,
                              void* d_out, int out_size)
{
    const float* x    = (const float*)d_in[0];
    const float* w_ih = (const float*)d_in[1];
    const float* w_hh = (const float*)d_in[2];
    const float* b_ih = (const float*)d_in[3];
    const float* b_hh = (const float*)d_in[4];
    const float* fc_w = (const float*)d_in[5];
    const float* fc_b = (const float*)d_in[6];
    float* out = (float*)d_out;

    const int B = 4096;
    const int S = in_sizes[0] / B;   // 2048

    // 6 elements per one-warp block
    const int blocks = (B + 5) / 6;  // 683

    lstm_pair_kernel<<<blocks, 32>>>(x, w_ih, w_hh, b_ih, b_hh,
                                     fc_w, fc_b, out, S, B);
}